// round 14
// baseline (speedup 1.0000x reference)
#include <cuda_runtime.h>
#include <cuda_fp16.h>
#include <math.h>
#include <stdint.h>

#define BDIM 2048
#define D 1024
#define C 8192
#define NB 64              // 8192 / 128 column blocks
#define NCHUNK 16          // 1024 / 64
#define BK 64              // k elems per chunk (128 bytes)
#define STAGE_BYTES 32768  // A(16KB) + B(16KB)
#define NSTAGE 3

// ---------------- scratch ----------------
__device__ __half g_A[(size_t)BDIM * D];     // xh
__device__ __half g_B[(size_t)C * D];        // ch
__device__ float g_c2[C];
__device__ float g_pmax[BDIM * NB];
__device__ int   g_pidx[BDIM * NB];
__device__ float g_psum[BDIM * NB];
__device__ float g_sy[BDIM];
__device__ float g_bloss[64];
__device__ float g_bmatch[64];
__device__ int   g_count;   // zero-init; last block resets (graph-replay safe)

// ---------------- helpers ----------------
__device__ __forceinline__ uint32_t smem_u32(const void* p) {
    uint32_t a;
    asm("{ .reg .u64 t; cvta.to.shared.u64 t, %1; cvt.u32.u64 %0, t; }" : "=r"(a) : "l"(p));
    return a;
}
#define CP_COMMIT() asm volatile("cp.async.commit_group;" ::: "memory")
#define CP_WAIT(n)  asm volatile("cp.async.wait_group %0;" :: "n"(n) : "memory")

__device__ __forceinline__ void ldsm_x4(uint32_t& r0, uint32_t& r1, uint32_t& r2, uint32_t& r3,
                                        uint32_t addr) {
    asm volatile("ldmatrix.sync.aligned.m8n8.x4.shared.b16 {%0,%1,%2,%3}, [%4];"
                 : "=r"(r0), "=r"(r1), "=r"(r2), "=r"(r3) : "r"(addr));
}
__device__ __forceinline__ void mma_f16(float* d, uint32_t a0, uint32_t a1, uint32_t a2,
                                        uint32_t a3, uint32_t b0, uint32_t b1) {
    asm volatile(
        "mma.sync.aligned.m16n8k16.row.col.f32.f16.f16.f32 "
        "{%0,%1,%2,%3}, {%4,%5,%6,%7}, {%8,%9}, {%0,%1,%2,%3};"
        : "+f"(d[0]), "+f"(d[1]), "+f"(d[2]), "+f"(d[3])
        : "r"(a0), "r"(a1), "r"(a2), "r"(a3), "r"(b0), "r"(b1));
}

// pack 8 floats -> 4x half2 in a uint4
__device__ __forceinline__ uint4 pack8(float4 a, float4 b) {
    union { __half2 h[4]; uint4 u; } r;
    r.h[0] = __halves2half2(__float2half(a.x), __float2half(a.y));
    r.h[1] = __halves2half2(__float2half(a.z), __float2half(a.w));
    r.h[2] = __halves2half2(__float2half(b.x), __float2half(b.y));
    r.h[3] = __halves2half2(__float2half(b.z), __float2half(b.w));
    return r.u;
}

// ---------------- prep: 2 warps per row (half-row each), 16B stores ----------------
__global__ void prep_kernel(const float* __restrict__ x, const float* __restrict__ cent) {
    __shared__ float c2h[8];
    const int warp = threadIdx.x >> 5, lane = threadIdx.x & 31;
    const int lrow = warp >> 1;              // 0..3 local row
    const int half = warp & 1;
    const int gr = blockIdx.x * 4 + lrow;    // global row id over [x ; cent]
    const bool isX = gr < BDIM;
    const int row = isX ? gr : gr - BDIM;
    const float4* src = (const float4*)((isX ? x : cent) + (size_t)row * D) + half * 128;
    uint4* o = (uint4*)((isX ? g_A : g_B) + (size_t)row * D) + half * 64;

    float s = 0.f;
    #pragma unroll
    for (int i = 0; i < 2; i++) {
        float4 a = src[i * 64 + lane * 2];
        float4 b = src[i * 64 + lane * 2 + 1];
        o[i * 32 + lane] = pack8(a, b);
        if (!isX) {
            s += a.x*a.x + a.y*a.y + a.z*a.z + a.w*a.w;
            s += b.x*b.x + b.y*b.y + b.z*b.z + b.w*b.w;
        }
    }
    if (!isX) {
        #pragma unroll
        for (int o2 = 16; o2 > 0; o2 >>= 1) s += __shfl_down_sync(0xffffffffu, s, o2);
        if (lane == 0) c2h[warp] = s;
        __syncthreads();
        if (lane == 0 && half == 0) g_c2[row] = c2h[warp] + c2h[warp + 1];
    }
}

// ---------------- main GEMM: 128x128 tile, 4 warps (2x2), warp tile 64x64 ----------
__device__ __forceinline__ void load_chunk(int mb, int nb, int c, uint32_t stage_base, int tid) {
    #pragma unroll
    for (int i = 0; i < 16; i++) {
        int seg_id = tid + (i << 7);          // 0..2047
        int region = seg_id >> 10;            // 0=A, 1=B
        int row = (seg_id >> 3) & 127;
        int seg = seg_id & 7;
        uint32_t dst = stage_base + (region ? 16384u : 0u)
                     + (uint32_t)(row * 128 + ((seg ^ (row & 7)) << 4));
        const __half* src =
            (region ? g_B + (size_t)(nb * 128 + row) * D
                    : g_A + (size_t)(mb * 128 + row) * D) + c * BK + seg * 8;
        asm volatile("cp.async.cg.shared.global [%0], [%1], 16;" :: "r"(dst), "l"(src) : "memory");
    }
}

__global__ __launch_bounds__(128, 2) void gemm_kernel(const int* __restrict__ y) {
    extern __shared__ char dsm[];
    __shared__ float c2s[128];
    __shared__ int   ybuf[128];

    const int nb = blockIdx.x;     // 0..63
    const int mb = blockIdx.y;     // 0..15
    const int tid = threadIdx.x;   // 0..127
    const int wid = tid >> 5, lane = tid & 31;
    const int wm = wid >> 1;       // 0..1
    const int wn = wid & 1;        // 0..1
    const uint32_t dbase = smem_u32(dsm);

    c2s[tid] = g_c2[nb * 128 + tid];
    ybuf[tid] = y[mb * 128 + tid];

    float acc[4][8][4];            // mt x nt x frag  (warp tile 64x64)
    #pragma unroll
    for (int i = 0; i < 4; i++)
        #pragma unroll
        for (int j = 0; j < 8; j++)
            #pragma unroll
            for (int e = 0; e < 4; e++) acc[i][j][e] = 0.f;

    const int a_row = wm * 64 + (lane & 15);
    const int a_hi  = lane >> 4;
    const int b_rowb = wn * 64 + (lane & 7) + ((lane >> 3) & 1) * 8;
    const int b_hi  = lane >> 4;

    #pragma unroll
    for (int p = 0; p < 2; p++) {
        load_chunk(mb, nb, p, dbase + p * STAGE_BYTES, tid);
        CP_COMMIT();
    }

    #pragma unroll
    for (int k = 0; k < NCHUNK; k++) {
        const uint32_t stage = dbase + (k % 3) * STAGE_BYTES;
        if (k < NCHUNK - 1) CP_WAIT(1);
        else CP_WAIT(0);
        __syncthreads();

        #pragma unroll
        for (int kk = 0; kk < 4; kk++) {
            uint32_t a[4][4], b0[8], b1[8];
            #pragma unroll
            for (int mt = 0; mt < 4; mt++) {
                int row = a_row + mt * 16;
                int seg = (kk * 2 + a_hi) ^ (row & 7);
                ldsm_x4(a[mt][0], a[mt][1], a[mt][2], a[mt][3],
                        stage + (uint32_t)(row * 128 + (seg << 4)));
            }
            #pragma unroll
            for (int nt2 = 0; nt2 < 4; nt2++) {
                int row = b_rowb + nt2 * 16;
                int seg = (kk * 2 + b_hi) ^ (row & 7);
                uint32_t r0, r1, r2, r3;
                ldsm_x4(r0, r1, r2, r3,
                        stage + 16384u + (uint32_t)(row * 128 + (seg << 4)));
                b0[nt2 * 2] = r0; b1[nt2 * 2] = r2;
                b0[nt2 * 2 + 1] = r1; b1[nt2 * 2 + 1] = r3;
            }
            #pragma unroll
            for (int mt = 0; mt < 4; mt++)
                #pragma unroll
                for (int nt = 0; nt < 8; nt++)
                    mma_f16(acc[mt][nt], a[mt][0], a[mt][1], a[mt][2], a[mt][3],
                            b0[nt], b1[nt]);
        }

        if (k + 2 < NCHUNK) {
            load_chunk(mb, nb, k + 2, dbase + ((k + 2) % 3) * STAGE_BYTES, tid);
            CP_COMMIT();
        }
    }
    __syncthreads();   // mainloop smem reads done; dsm reusable

    // ---- in-register epilogue: online softmax partials from acc fragments ----
    float* red_m = (float*)dsm;               // [128][2]
    int*   red_i = (int*)(dsm + 1024);        // [128][2]
    float* red_s = (float*)(dsm + 2048);      // [128][2]

    const int q  = lane >> 2;
    const int c4 = (lane & 3) * 2;
    #pragma unroll
    for (int mt = 0; mt < 4; mt++) {
        #pragma unroll
        for (int h = 0; h < 2; h++) {
            const int r  = wm * 64 + mt * 16 + h * 8 + q;   // local row
            const int yv = ybuf[r];
            float m = -INFINITY, ssum = 0.f; int mi = 0;
            #pragma unroll
            for (int nt = 0; nt < 8; nt++) {
                #pragma unroll
                for (int e = 0; e < 2; e++) {
                    int lcol = wn * 64 + nt * 8 + c4 + e;
                    float sv = fmaf(2.f, acc[mt][nt][h * 2 + e], -c2s[lcol]);
                    int col = nb * 128 + lcol;
                    if (sv > m) { ssum = ssum * __expf(m - sv) + 1.f; m = sv; mi = col; }
                    else ssum += __expf(sv - m);
                    if (col == yv) g_sy[mb * 128 + r] = sv;
                }
            }
            #pragma unroll
            for (int o = 1; o <= 2; o <<= 1) {
                float m2 = __shfl_xor_sync(0xffffffffu, m, o);
                int  mi2 = __shfl_xor_sync(0xffffffffu, mi, o);
                float s2 = __shfl_xor_sync(0xffffffffu, ssum, o);
                bool take = (m2 > m) || (m2 == m && mi2 < mi);
                float M = take ? m2 : m;
                int  MI = take ? mi2 : mi;
                ssum = ssum * __expf(m - M) + s2 * __expf(m2 - M);
                m = M; mi = MI;
            }
            if ((lane & 3) == 0) {
                red_m[r * 2 + wn] = m; red_i[r * 2 + wn] = mi; red_s[r * 2 + wn] = ssum;
            }
        }
    }
    __syncthreads();
    {
        float m = -INFINITY, S = 0.f; int mi = 0x7fffffff;
        #pragma unroll
        for (int w = 0; w < 2; w++) {
            float m2 = red_m[tid * 2 + w]; int i2 = red_i[tid * 2 + w]; float s2 = red_s[tid * 2 + w];
            bool take = (m2 > m) || (m2 == m && i2 < mi);
            float M = take ? m2 : m;
            int  MI = take ? i2 : mi;
            S = S * __expf(m - M) + s2 * __expf(m2 - M);
            m = M; mi = MI;
        }
        int row = mb * 128 + tid;
        g_pmax[(size_t)row * NB + nb] = m;
        g_pidx[(size_t)row * NB + nb] = mi;
        g_psum[(size_t)row * NB + nb] = S;
    }
}

// ---------------- fused merge + final: 64 blocks, last block reduces ----------------
__global__ void merge_final_kernel(const int* __restrict__ y, float* __restrict__ out,
                                   int out_size) {
    const int tid = threadIdx.x, bid = blockIdx.x;
    const int rl = tid >> 3;              // local row 0..31
    const int sub = tid & 7;
    const int row = bid * 32 + rl;
    const size_t base = (size_t)row * NB;

    float m = -INFINITY; int mi = 0x7fffffff;
    #pragma unroll
    for (int p = sub; p < NB; p += 8) {
        float v = g_pmax[base + p]; int ix = g_pidx[base + p];
        if (v > m || (v == m && ix < mi)) { m = v; mi = ix; }
    }
    #pragma unroll
    for (int o = 4; o > 0; o >>= 1) {
        float vo = __shfl_down_sync(0xffffffffu, m, o, 8);
        int   io = __shfl_down_sync(0xffffffffu, mi, o, 8);
        if (vo > m || (vo == m && io < mi)) { m = vo; mi = io; }
    }
    m  = __shfl_sync(0xffffffffu, m, 0, 8);
    mi = __shfl_sync(0xffffffffu, mi, 0, 8);

    float tot = 0.f;
    #pragma unroll
    for (int p = sub; p < NB; p += 8)
        tot += g_psum[base + p] * __expf(g_pmax[base + p] - m);
    #pragma unroll
    for (int o = 4; o > 0; o >>= 1) tot += __shfl_down_sync(0xffffffffu, tot, o, 8);

    __shared__ float sl[32], sm_[32];
    if (sub == 0) {
        float lse = m + logf(tot);
        sl[rl]  = lse - g_sy[row];
        sm_[rl] = (mi == y[row]) ? 1.f : 0.f;
    }
    __syncthreads();
    if (tid == 0) {
        float L = 0.f, M = 0.f;
        #pragma unroll
        for (int i = 0; i < 32; i++) { L += sl[i]; M += sm_[i]; }
        g_bloss[bid] = L; g_bmatch[bid] = M;
        __threadfence();
        int old = atomicAdd(&g_count, 1);
        if (old == 63) {
            __threadfence();
            float TL = 0.f, TM = 0.f;
            for (int i = 0; i < 64; i++) { TL += g_bloss[i]; TM += g_bmatch[i]; }
            out[0] = TL / (float)BDIM;
            if (out_size > 1) out[1] = TM / (float)BDIM;
            g_count = 0;   // reset for next graph replay
        }
    }
}

// ---------------- launch ----------------
extern "C" void kernel_launch(void* const* d_in, const int* in_sizes, int n_in,
                              void* d_out, int out_size) {
    const float* x    = (const float*)d_in[0];
    const int*   y    = (const int*)d_in[1];
    const float* cent = (const float*)d_in[2];
    float* out = (float*)d_out;

    cudaFuncSetAttribute(gemm_kernel, cudaFuncAttributeMaxDynamicSharedMemorySize,
                         NSTAGE * STAGE_BYTES);

    prep_kernel<<<(BDIM + C) / 4, 256>>>(x, cent);
    gemm_kernel<<<dim3(NB, BDIM / 128), 128, NSTAGE * STAGE_BYTES>>>(y);
    merge_final_kernel<<<64, 256>>>(y, out, out_size);
}

// round 15
// speedup vs baseline: 1.3348x; 1.3348x over previous
#include <cuda_runtime.h>
#include <cuda_fp16.h>
#include <math.h>
#include <stdint.h>

#define BDIM 2048
#define D 1024
#define C 8192
#define NB 64              // 8192 / 128 column blocks
#define NCHUNK 16          // 1024 / 64
#define BK 64              // k elems per chunk (128 bytes)
#define STAGE_BYTES 32768  // A(16KB) + B(16KB)
#define NSTAGE 3

// ---------------- scratch ----------------
__device__ __half g_A[(size_t)BDIM * D];     // xh
__device__ __half g_B[(size_t)C * D];        // ch
__device__ float g_c2[C];
__device__ float g_pmax[BDIM * NB];
__device__ int   g_pidx[BDIM * NB];
__device__ float g_psum[BDIM * NB];
__device__ float g_sy[BDIM];
__device__ float g_bloss[64];
__device__ float g_bmatch[64];
__device__ int   g_count;   // zero-init; last block resets (graph-replay safe)

// ---------------- helpers ----------------
__device__ __forceinline__ uint32_t smem_u32(const void* p) {
    uint32_t a;
    asm("{ .reg .u64 t; cvta.to.shared.u64 t, %1; cvt.u32.u64 %0, t; }" : "=r"(a) : "l"(p));
    return a;
}
#define CP_COMMIT() asm volatile("cp.async.commit_group;" ::: "memory")
#define CP_WAIT(n)  asm volatile("cp.async.wait_group %0;" :: "n"(n) : "memory")

__device__ __forceinline__ void ldsm_x4(uint32_t& r0, uint32_t& r1, uint32_t& r2, uint32_t& r3,
                                        uint32_t addr) {
    asm volatile("ldmatrix.sync.aligned.m8n8.x4.shared.b16 {%0,%1,%2,%3}, [%4];"
                 : "=r"(r0), "=r"(r1), "=r"(r2), "=r"(r3) : "r"(addr));
}
__device__ __forceinline__ void mma_f16(float* d, uint32_t a0, uint32_t a1, uint32_t a2,
                                        uint32_t a3, uint32_t b0, uint32_t b1) {
    asm volatile(
        "mma.sync.aligned.m16n8k16.row.col.f32.f16.f16.f32 "
        "{%0,%1,%2,%3}, {%4,%5,%6,%7}, {%8,%9}, {%0,%1,%2,%3};"
        : "+f"(d[0]), "+f"(d[1]), "+f"(d[2]), "+f"(d[3])
        : "r"(a0), "r"(a1), "r"(a2), "r"(a3), "r"(b0), "r"(b1));
}

// pack 8 floats -> 4x half2 in a uint4
__device__ __forceinline__ uint4 pack8(float4 a, float4 b) {
    union { __half2 h[4]; uint4 u; } r;
    r.h[0] = __halves2half2(__float2half(a.x), __float2half(a.y));
    r.h[1] = __halves2half2(__float2half(a.z), __float2half(a.w));
    r.h[2] = __halves2half2(__float2half(b.x), __float2half(b.y));
    r.h[3] = __halves2half2(__float2half(b.z), __float2half(b.w));
    return r.u;
}

// ---------------- prep: 2 warps per row (half-row each), 16B stores ----------------
__global__ void prep_kernel(const float* __restrict__ x, const float* __restrict__ cent) {
    __shared__ float c2h[8];
    const int warp = threadIdx.x >> 5, lane = threadIdx.x & 31;
    const int lrow = warp >> 1;              // 0..3 local row
    const int half = warp & 1;
    const int gr = blockIdx.x * 4 + lrow;    // global row id over [x ; cent]
    const bool isX = gr < BDIM;
    const int row = isX ? gr : gr - BDIM;
    const float4* src = (const float4*)((isX ? x : cent) + (size_t)row * D) + half * 128;
    uint4* o = (uint4*)((isX ? g_A : g_B) + (size_t)row * D) + half * 64;

    float s = 0.f;
    #pragma unroll
    for (int i = 0; i < 2; i++) {
        float4 a = src[i * 64 + lane * 2];
        float4 b = src[i * 64 + lane * 2 + 1];
        o[i * 32 + lane] = pack8(a, b);
        if (!isX) {
            s += a.x*a.x + a.y*a.y + a.z*a.z + a.w*a.w;
            s += b.x*b.x + b.y*b.y + b.z*b.z + b.w*b.w;
        }
    }
    if (!isX) {
        #pragma unroll
        for (int o2 = 16; o2 > 0; o2 >>= 1) s += __shfl_down_sync(0xffffffffu, s, o2);
        if (lane == 0) c2h[warp] = s;
        __syncthreads();
        if (lane == 0 && half == 0) g_c2[row] = c2h[warp] + c2h[warp + 1];
    }
}

// ---------------- main GEMM: mma.sync fp16, 128x128 tile, 3-stage, 2 CTA/SM ----
__device__ __forceinline__ void load_chunk(int mb, int nb, int c, uint32_t stage_base, int tid) {
    #pragma unroll
    for (int i = 0; i < 8; i++) {
        int seg_id = tid + (i << 8);          // 0..2047
        int region = seg_id >> 10;            // 0=A, 1=B
        int row = (seg_id >> 3) & 127;
        int seg = seg_id & 7;
        uint32_t dst = stage_base + (region ? 16384u : 0u)
                     + (uint32_t)(row * 128 + ((seg ^ (row & 7)) << 4));
        const __half* src =
            (region ? g_B + (size_t)(nb * 128 + row) * D
                    : g_A + (size_t)(mb * 128 + row) * D) + c * BK + seg * 8;
        asm volatile("cp.async.cg.shared.global [%0], [%1], 16;" :: "r"(dst), "l"(src) : "memory");
    }
}

__global__ __launch_bounds__(256, 2) void gemm_kernel(const int* __restrict__ y) {
    extern __shared__ char dsm[];
    __shared__ float c2s[128];
    __shared__ int   ybuf[128];

    const int nb = blockIdx.x;     // 0..63
    const int mb = blockIdx.y;     // 0..15
    const int tid = threadIdx.x;
    const int wid = tid >> 5, lane = tid & 31;
    const int wm = wid >> 2;       // 0..1
    const int wn = wid & 3;        // 0..3
    const uint32_t dbase = smem_u32(dsm);

    if (tid < 128) { c2s[tid] = g_c2[nb * 128 + tid]; ybuf[tid] = y[mb * 128 + tid]; }

    float acc[4][4][4];
    #pragma unroll
    for (int i = 0; i < 4; i++)
        #pragma unroll
        for (int j = 0; j < 4; j++)
            #pragma unroll
            for (int e = 0; e < 4; e++) acc[i][j][e] = 0.f;

    const int a_row = wm * 64 + (lane & 15);
    const int a_hi  = lane >> 4;
    const int b_row = wn * 32 + (lane & 7) + ((lane >> 3) & 1) * 8;
    const int b_hi  = lane >> 4;

    #pragma unroll
    for (int p = 0; p < 2; p++) {
        load_chunk(mb, nb, p, dbase + p * STAGE_BYTES, tid);
        CP_COMMIT();
    }

    #pragma unroll
    for (int k = 0; k < NCHUNK; k++) {
        const uint32_t stage = dbase + (k % 3) * STAGE_BYTES;
        if (k < NCHUNK - 1) CP_WAIT(1);
        else CP_WAIT(0);
        __syncthreads();

        // issue next chunk's loads FIRST: stage (k+2)%3 is free (the sync proves
        // every warp is done reading it), and loads get a full compute phase of
        // head start before CP_WAIT needs them.
        if (k + 2 < NCHUNK) {
            load_chunk(mb, nb, k + 2, dbase + ((k + 2) % 3) * STAGE_BYTES, tid);
            CP_COMMIT();
        }

        #pragma unroll
        for (int kk = 0; kk < 4; kk++) {
            uint32_t a[4][4], b0[4], b1[4];
            #pragma unroll
            for (int mt = 0; mt < 4; mt++) {
                int row = a_row + mt * 16;
                int seg = (kk * 2 + a_hi) ^ (row & 7);
                ldsm_x4(a[mt][0], a[mt][1], a[mt][2], a[mt][3],
                        stage + (uint32_t)(row * 128 + (seg << 4)));
            }
            #pragma unroll
            for (int nt2 = 0; nt2 < 2; nt2++) {
                int row = b_row + nt2 * 16;
                int seg = (kk * 2 + b_hi) ^ (row & 7);
                uint32_t r0, r1, r2, r3;
                ldsm_x4(r0, r1, r2, r3,
                        stage + 16384u + (uint32_t)(row * 128 + (seg << 4)));
                b0[nt2 * 2] = r0; b1[nt2 * 2] = r2;
                b0[nt2 * 2 + 1] = r1; b1[nt2 * 2 + 1] = r3;
            }
            #pragma unroll
            for (int mt = 0; mt < 4; mt++)
                #pragma unroll
                for (int nt = 0; nt < 4; nt++)
                    mma_f16(acc[mt][nt], a[mt][0], a[mt][1], a[mt][2], a[mt][3],
                            b0[nt], b1[nt]);
        }
    }
    __syncthreads();   // mainloop smem reads done; dsm reusable

    // ---- in-register epilogue: online softmax partials from acc fragments ----
    float* red_m = (float*)dsm;               // [128][4]
    int*   red_i = (int*)(dsm + 2048);        // [128][4]
    float* red_s = (float*)(dsm + 4096);      // [128][4]

    const int q  = lane >> 2;
    const int c4 = (lane & 3) * 2;
    #pragma unroll
    for (int mt = 0; mt < 4; mt++) {
        #pragma unroll
        for (int h = 0; h < 2; h++) {
            const int r  = wm * 64 + mt * 16 + h * 8 + q;   // local row
            const int yv = ybuf[r];
            float m = -INFINITY, ssum = 0.f; int mi = 0;
            #pragma unroll
            for (int nt = 0; nt < 4; nt++) {
                #pragma unroll
                for (int e = 0; e < 2; e++) {
                    int lcol = wn * 32 + nt * 8 + c4 + e;
                    float sv = fmaf(2.f, acc[mt][nt][h * 2 + e], -c2s[lcol]);
                    int col = nb * 128 + lcol;
                    if (sv > m) { ssum = ssum * __expf(m - sv) + 1.f; m = sv; mi = col; }
                    else ssum += __expf(sv - m);
                    if (col == yv) g_sy[mb * 128 + r] = sv;
                }
            }
            #pragma unroll
            for (int o = 1; o <= 2; o <<= 1) {
                float m2 = __shfl_xor_sync(0xffffffffu, m, o);
                int  mi2 = __shfl_xor_sync(0xffffffffu, mi, o);
                float s2 = __shfl_xor_sync(0xffffffffu, ssum, o);
                bool take = (m2 > m) || (m2 == m && mi2 < mi);
                float M = take ? m2 : m;
                int  MI = take ? mi2 : mi;
                ssum = ssum * __expf(m - M) + s2 * __expf(m2 - M);
                m = M; mi = MI;
            }
            if ((lane & 3) == 0) {
                red_m[r * 4 + wn] = m; red_i[r * 4 + wn] = mi; red_s[r * 4 + wn] = ssum;
            }
        }
    }
    __syncthreads();
    if (tid < 128) {
        float m = -INFINITY, S = 0.f; int mi = 0x7fffffff;
        #pragma unroll
        for (int w = 0; w < 4; w++) {
            float m2 = red_m[tid * 4 + w]; int i2 = red_i[tid * 4 + w]; float s2 = red_s[tid * 4 + w];
            bool take = (m2 > m) || (m2 == m && i2 < mi);
            float M = take ? m2 : m;
            int  MI = take ? i2 : mi;
            S = S * __expf(m - M) + s2 * __expf(m2 - M);
            m = M; mi = MI;
        }
        int row = mb * 128 + tid;
        g_pmax[(size_t)row * NB + nb] = m;
        g_pidx[(size_t)row * NB + nb] = mi;
        g_psum[(size_t)row * NB + nb] = S;
    }
}

// ---------------- fused merge + final: 64 blocks, last block reduces ----------------
__global__ void merge_final_kernel(const int* __restrict__ y, float* __restrict__ out,
                                   int out_size) {
    const int tid = threadIdx.x, bid = blockIdx.x;
    const int rl = tid >> 3;              // local row 0..31
    const int sub = tid & 7;
    const int row = bid * 32 + rl;
    const size_t base = (size_t)row * NB;

    float m = -INFINITY; int mi = 0x7fffffff;
    #pragma unroll
    for (int p = sub; p < NB; p += 8) {
        float v = g_pmax[base + p]; int ix = g_pidx[base + p];
        if (v > m || (v == m && ix < mi)) { m = v; mi = ix; }
    }
    #pragma unroll
    for (int o = 4; o > 0; o >>= 1) {
        float vo = __shfl_down_sync(0xffffffffu, m, o, 8);
        int   io = __shfl_down_sync(0xffffffffu, mi, o, 8);
        if (vo > m || (vo == m && io < mi)) { m = vo; mi = io; }
    }
    m  = __shfl_sync(0xffffffffu, m, 0, 8);
    mi = __shfl_sync(0xffffffffu, mi, 0, 8);

    float tot = 0.f;
    #pragma unroll
    for (int p = sub; p < NB; p += 8)
        tot += g_psum[base + p] * __expf(g_pmax[base + p] - m);
    #pragma unroll
    for (int o = 4; o > 0; o >>= 1) tot += __shfl_down_sync(0xffffffffu, tot, o, 8);

    __shared__ float sl[32], sm_[32];
    if (sub == 0) {
        float lse = m + logf(tot);
        sl[rl]  = lse - g_sy[row];
        sm_[rl] = (mi == y[row]) ? 1.f : 0.f;
    }
    __syncthreads();
    if (tid == 0) {
        float L = 0.f, M = 0.f;
        #pragma unroll
        for (int i = 0; i < 32; i++) { L += sl[i]; M += sm_[i]; }
        g_bloss[bid] = L; g_bmatch[bid] = M;
        __threadfence();
        int old = atomicAdd(&g_count, 1);
        if (old == 63) {
            __threadfence();
            float TL = 0.f, TM = 0.f;
            for (int i = 0; i < 64; i++) { TL += g_bloss[i]; TM += g_bmatch[i]; }
            out[0] = TL / (float)BDIM;
            if (out_size > 1) out[1] = TM / (float)BDIM;
            g_count = 0;   // reset for next graph replay
        }
    }
}

// ---------------- launch ----------------
extern "C" void kernel_launch(void* const* d_in, const int* in_sizes, int n_in,
                              void* d_out, int out_size) {
    const float* x    = (const float*)d_in[0];
    const int*   y    = (const int*)d_in[1];
    const float* cent = (const float*)d_in[2];
    float* out = (float*)d_out;

    cudaFuncSetAttribute(gemm_kernel, cudaFuncAttributeMaxDynamicSharedMemorySize,
                         NSTAGE * STAGE_BYTES);

    prep_kernel<<<(BDIM + C) / 4, 256>>>(x, cent);
    gemm_kernel<<<dim3(NB, BDIM / 128), 256, NSTAGE * STAGE_BYTES>>>(y);
    merge_final_kernel<<<64, 256>>>(y, out, out_size);
}

// round 16
// speedup vs baseline: 1.3618x; 1.0203x over previous
#include <cuda_runtime.h>
#include <cuda_fp16.h>
#include <math.h>
#include <stdint.h>

#define BDIM 2048
#define D 1024
#define C 8192
#define NB 64              // 8192 / 128 column blocks
#define NCHUNK 16          // 1024 / 64
#define BK 64              // k elems per chunk (128 bytes)
#define STAGE_BYTES 32768  // A(16KB) + B(16KB)
#define NSTAGE 3

// ---------------- scratch ----------------
__device__ __half g_A[(size_t)BDIM * D];     // xh
__device__ __half g_B[(size_t)C * D];        // ch
__device__ float g_c2[C];
__device__ float g_pmax[BDIM * NB];
__device__ int   g_pidx[BDIM * NB];
__device__ float g_psum[BDIM * NB];
__device__ float g_sy[BDIM];
__device__ float g_bloss[64];
__device__ float g_bmatch[64];
__device__ int   g_count;   // zero-init; last block resets (graph-replay safe)

// ---------------- helpers ----------------
__device__ __forceinline__ uint32_t smem_u32(const void* p) {
    uint32_t a;
    asm("{ .reg .u64 t; cvta.to.shared.u64 t, %1; cvt.u32.u64 %0, t; }" : "=r"(a) : "l"(p));
    return a;
}
#define CP_COMMIT() asm volatile("cp.async.commit_group;" ::: "memory")
#define CP_WAIT(n)  asm volatile("cp.async.wait_group %0;" :: "n"(n) : "memory")

__device__ __forceinline__ void ldsm_x4(uint32_t& r0, uint32_t& r1, uint32_t& r2, uint32_t& r3,
                                        uint32_t addr) {
    asm volatile("ldmatrix.sync.aligned.m8n8.x4.shared.b16 {%0,%1,%2,%3}, [%4];"
                 : "=r"(r0), "=r"(r1), "=r"(r2), "=r"(r3) : "r"(addr));
}
__device__ __forceinline__ void mma_f16(float* d, uint32_t a0, uint32_t a1, uint32_t a2,
                                        uint32_t a3, uint32_t b0, uint32_t b1) {
    asm volatile(
        "mma.sync.aligned.m16n8k16.row.col.f32.f16.f16.f32 "
        "{%0,%1,%2,%3}, {%4,%5,%6,%7}, {%8,%9}, {%0,%1,%2,%3};"
        : "+f"(d[0]), "+f"(d[1]), "+f"(d[2]), "+f"(d[3])
        : "r"(a0), "r"(a1), "r"(a2), "r"(a3), "r"(b0), "r"(b1));
}

// pack 8 floats -> 4x half2 in a uint4
__device__ __forceinline__ uint4 pack8(float4 a, float4 b) {
    union { __half2 h[4]; uint4 u; } r;
    r.h[0] = __halves2half2(__float2half(a.x), __float2half(a.y));
    r.h[1] = __halves2half2(__float2half(a.z), __float2half(a.w));
    r.h[2] = __halves2half2(__float2half(b.x), __float2half(b.y));
    r.h[3] = __halves2half2(__float2half(b.z), __float2half(b.w));
    return r.u;
}

// ---------------- prep: 2 warps per row (half-row each), 16B stores ----------------
__global__ void prep_kernel(const float* __restrict__ x, const float* __restrict__ cent) {
    __shared__ float c2h[8];
    const int warp = threadIdx.x >> 5, lane = threadIdx.x & 31;
    const int lrow = warp >> 1;              // 0..3 local row
    const int half = warp & 1;
    const int gr = blockIdx.x * 4 + lrow;    // global row id over [x ; cent]
    const bool isX = gr < BDIM;
    const int row = isX ? gr : gr - BDIM;
    const float4* src = (const float4*)((isX ? x : cent) + (size_t)row * D) + half * 128;
    uint4* o = (uint4*)((isX ? g_A : g_B) + (size_t)row * D) + half * 64;

    float s = 0.f;
    #pragma unroll
    for (int i = 0; i < 2; i++) {
        float4 a = src[i * 64 + lane * 2];
        float4 b = src[i * 64 + lane * 2 + 1];
        o[i * 32 + lane] = pack8(a, b);
        if (!isX) {
            s += a.x*a.x + a.y*a.y + a.z*a.z + a.w*a.w;
            s += b.x*b.x + b.y*b.y + b.z*b.z + b.w*b.w;
        }
    }
    if (!isX) {
        #pragma unroll
        for (int o2 = 16; o2 > 0; o2 >>= 1) s += __shfl_down_sync(0xffffffffu, s, o2);
        if (lane == 0) c2h[warp] = s;
        __syncthreads();
        if (lane == 0 && half == 0) g_c2[row] = c2h[warp] + c2h[warp + 1];
    }
}

// ---------------- main GEMM: mma.sync fp16, 128x128 tile, 3-stage, 2 CTA/SM ----
__device__ __forceinline__ void load_chunk(int mb, int nb, int c, uint32_t stage_base, int tid) {
    #pragma unroll
    for (int i = 0; i < 8; i++) {
        int seg_id = tid + (i << 8);          // 0..2047
        int region = seg_id >> 10;            // 0=A, 1=B
        int row = (seg_id >> 3) & 127;
        int seg = seg_id & 7;
        uint32_t dst = stage_base + (region ? 16384u : 0u)
                     + (uint32_t)(row * 128 + ((seg ^ (row & 7)) << 4));
        const __half* src =
            (region ? g_B + (size_t)(nb * 128 + row) * D
                    : g_A + (size_t)(mb * 128 + row) * D) + c * BK + seg * 8;
        asm volatile("cp.async.cg.shared.global [%0], [%1], 16;" :: "r"(dst), "l"(src) : "memory");
    }
}

__global__ __launch_bounds__(256, 2) void gemm_kernel(const int* __restrict__ y) {
    extern __shared__ char dsm[];
    __shared__ float c2s[128];
    __shared__ int   ybuf[128];

    const int nb = blockIdx.x;     // 0..63
    const int mb = blockIdx.y;     // 0..15
    const int tid = threadIdx.x;
    const int wid = tid >> 5, lane = tid & 31;
    const int wm = wid >> 2;       // 0..1
    const int wn = wid & 3;        // 0..3
    const uint32_t dbase = smem_u32(dsm);

    if (tid < 128) { c2s[tid] = g_c2[nb * 128 + tid]; ybuf[tid] = y[mb * 128 + tid]; }

    float acc[4][4][4];
    #pragma unroll
    for (int i = 0; i < 4; i++)
        #pragma unroll
        for (int j = 0; j < 4; j++)
            #pragma unroll
            for (int e = 0; e < 4; e++) acc[i][j][e] = 0.f;

    const int a_row = wm * 64 + (lane & 15);
    const int a_hi  = lane >> 4;
    const int b_row = wn * 32 + (lane & 7) + ((lane >> 3) & 1) * 8;
    const int b_hi  = lane >> 4;

    #pragma unroll
    for (int p = 0; p < 2; p++) {
        load_chunk(mb, nb, p, dbase + p * STAGE_BYTES, tid);
        CP_COMMIT();
    }

    #pragma unroll
    for (int k = 0; k < NCHUNK; k++) {
        const uint32_t stage = dbase + (k % 3) * STAGE_BYTES;
        if (k < NCHUNK - 1) CP_WAIT(1);
        else CP_WAIT(0);
        __syncthreads();   // protects stage reuse by the load below

        #pragma unroll
        for (int kk = 0; kk < 4; kk++) {
            uint32_t a[4][4], b0[4], b1[4];
            #pragma unroll
            for (int mt = 0; mt < 4; mt++) {
                int row = a_row + mt * 16;
                int seg = (kk * 2 + a_hi) ^ (row & 7);
                ldsm_x4(a[mt][0], a[mt][1], a[mt][2], a[mt][3],
                        stage + (uint32_t)(row * 128 + (seg << 4)));
            }
            #pragma unroll
            for (int nt2 = 0; nt2 < 2; nt2++) {
                int row = b_row + nt2 * 16;
                int seg = (kk * 2 + b_hi) ^ (row & 7);
                uint32_t r0, r1, r2, r3;
                ldsm_x4(r0, r1, r2, r3,
                        stage + 16384u + (uint32_t)(row * 128 + (seg << 4)));
                b0[nt2 * 2] = r0; b1[nt2 * 2] = r2;
                b0[nt2 * 2 + 1] = r1; b1[nt2 * 2 + 1] = r3;
            }
            #pragma unroll
            for (int mt = 0; mt < 4; mt++)
                #pragma unroll
                for (int nt = 0; nt < 4; nt++)
                    mma_f16(acc[mt][nt], a[mt][0], a[mt][1], a[mt][2], a[mt][3],
                            b0[nt], b1[nt]);
        }

        if (k + 2 < NCHUNK) {
            load_chunk(mb, nb, k + 2, dbase + ((k + 2) % 3) * STAGE_BYTES, tid);
            CP_COMMIT();
        }
    }
    __syncthreads();   // mainloop smem reads done; dsm reusable

    // ---- in-register epilogue: online softmax partials from acc fragments ----
    float* red_m = (float*)dsm;               // [128][4]
    int*   red_i = (int*)(dsm + 2048);        // [128][4]
    float* red_s = (float*)(dsm + 4096);      // [128][4]

    const int q  = lane >> 2;
    const int c4 = (lane & 3) * 2;
    #pragma unroll
    for (int mt = 0; mt < 4; mt++) {
        #pragma unroll
        for (int h = 0; h < 2; h++) {
            const int r  = wm * 64 + mt * 16 + h * 8 + q;   // local row
            const int yv = ybuf[r];
            float m = -INFINITY, ssum = 0.f; int mi = 0;
            #pragma unroll
            for (int nt = 0; nt < 4; nt++) {
                #pragma unroll
                for (int e = 0; e < 2; e++) {
                    int lcol = wn * 32 + nt * 8 + c4 + e;
                    float sv = fmaf(2.f, acc[mt][nt][h * 2 + e], -c2s[lcol]);
                    int col = nb * 128 + lcol;
                    if (sv > m) { ssum = ssum * __expf(m - sv) + 1.f; m = sv; mi = col; }
                    else ssum += __expf(sv - m);
                    if (col == yv) g_sy[mb * 128 + r] = sv;
                }
            }
            #pragma unroll
            for (int o = 1; o <= 2; o <<= 1) {
                float m2 = __shfl_xor_sync(0xffffffffu, m, o);
                int  mi2 = __shfl_xor_sync(0xffffffffu, mi, o);
                float s2 = __shfl_xor_sync(0xffffffffu, ssum, o);
                bool take = (m2 > m) || (m2 == m && mi2 < mi);
                float M = take ? m2 : m;
                int  MI = take ? mi2 : mi;
                ssum = ssum * __expf(m - M) + s2 * __expf(m2 - M);
                m = M; mi = MI;
            }
            if ((lane & 3) == 0) {
                red_m[r * 4 + wn] = m; red_i[r * 4 + wn] = mi; red_s[r * 4 + wn] = ssum;
            }
        }
    }
    __syncthreads();
    if (tid < 128) {
        float m = -INFINITY, S = 0.f; int mi = 0x7fffffff;
        #pragma unroll
        for (int w = 0; w < 4; w++) {
            float m2 = red_m[tid * 4 + w]; int i2 = red_i[tid * 4 + w]; float s2 = red_s[tid * 4 + w];
            bool take = (m2 > m) || (m2 == m && i2 < mi);
            float M = take ? m2 : m;
            int  MI = take ? i2 : mi;
            S = S * __expf(m - M) + s2 * __expf(m2 - M);
            m = M; mi = MI;
        }
        int row = mb * 128 + tid;
        g_pmax[(size_t)row * NB + nb] = m;
        g_pidx[(size_t)row * NB + nb] = mi;
        g_psum[(size_t)row * NB + nb] = S;
    }
}

// ---------------- fused merge + final: 64 blocks, last block reduces ----------------
__global__ void merge_final_kernel(const int* __restrict__ y, float* __restrict__ out,
                                   int out_size) {
    const int tid = threadIdx.x, bid = blockIdx.x;
    const int rl = tid >> 3;              // local row 0..31
    const int sub = tid & 7;
    const int row = bid * 32 + rl;
    const size_t base = (size_t)row * NB;

    float m = -INFINITY; int mi = 0x7fffffff;
    #pragma unroll
    for (int p = sub; p < NB; p += 8) {
        float v = g_pmax[base + p]; int ix = g_pidx[base + p];
        if (v > m || (v == m && ix < mi)) { m = v; mi = ix; }
    }
    #pragma unroll
    for (int o = 4; o > 0; o >>= 1) {
        float vo = __shfl_down_sync(0xffffffffu, m, o, 8);
        int   io = __shfl_down_sync(0xffffffffu, mi, o, 8);
        if (vo > m || (vo == m && io < mi)) { m = vo; mi = io; }
    }
    m  = __shfl_sync(0xffffffffu, m, 0, 8);
    mi = __shfl_sync(0xffffffffu, mi, 0, 8);

    float tot = 0.f;
    #pragma unroll
    for (int p = sub; p < NB; p += 8)
        tot += g_psum[base + p] * __expf(g_pmax[base + p] - m);
    #pragma unroll
    for (int o = 4; o > 0; o >>= 1) tot += __shfl_down_sync(0xffffffffu, tot, o, 8);

    __shared__ float sl[32], sm_[32];
    if (sub == 0) {
        float lse = m + logf(tot);
        sl[rl]  = lse - g_sy[row];
        sm_[rl] = (mi == y[row]) ? 1.f : 0.f;
    }
    __syncthreads();
    if (tid == 0) {
        float L = 0.f, M = 0.f;
        #pragma unroll
        for (int i = 0; i < 32; i++) { L += sl[i]; M += sm_[i]; }
        g_bloss[bid] = L; g_bmatch[bid] = M;
        __threadfence();
        int old = atomicAdd(&g_count, 1);
        if (old == 63) {
            __threadfence();
            float TL = 0.f, TM = 0.f;
            for (int i = 0; i < 64; i++) { TL += g_bloss[i]; TM += g_bmatch[i]; }
            out[0] = TL / (float)BDIM;
            if (out_size > 1) out[1] = TM / (float)BDIM;
            g_count = 0;   // reset for next graph replay
        }
    }
}

// ---------------- launch ----------------
extern "C" void kernel_launch(void* const* d_in, const int* in_sizes, int n_in,
                              void* d_out, int out_size) {
    const float* x    = (const float*)d_in[0];
    const int*   y    = (const int*)d_in[1];
    const float* cent = (const float*)d_in[2];
    float* out = (float*)d_out;

    cudaFuncSetAttribute(gemm_kernel, cudaFuncAttributeMaxDynamicSharedMemorySize,
                         NSTAGE * STAGE_BYTES);

    prep_kernel<<<(BDIM + C) / 4, 256>>>(x, cent);
    gemm_kernel<<<dim3(NB, BDIM / 128), 256, NSTAGE * STAGE_BYTES>>>(y);
    merge_final_kernel<<<64, 256>>>(y, out, out_size);
}